// round 1
// baseline (speedup 1.0000x reference)
#include <cuda_runtime.h>

// AtomicConv edge aggregation.
// he[e][j] = rbf(k, dist[e2]) * cutoff(dist[e2]) with k = e/EPB, e2 = 16*(e%EPB)+j
// out[dst[e]*128 + t*16 + j] += he[e][j] where t = one-hot index of feat[src[e]].

__global__ __launch_bounds__(256) void zero_out_kernel(float4* __restrict__ out, int n4) {
    int i = blockIdx.x * blockDim.x + threadIdx.x;
    if (i < n4) out[i] = make_float4(0.f, 0.f, 0.f, 0.f);
}

__device__ __forceinline__ float edge_weight(float d, float cut, float mean,
                                             float sc, float hpoc) {
    // 0.5*(cos(pi*d/cut)+1) == cos^2(pi*d/(2*cut)) : exact identity, no cancellation
    float c = __cosf(d * hpoc);
    float cv = c * c;
    cv = (d <= cut) ? cv : 0.f;
    float dm = d - mean;
    return cv * __expf(-sc * dm * dm);
}

__global__ __launch_bounds__(256) void acnn_edge_kernel(
    const float* __restrict__ dist,   // (E)
    const float* __restrict__ feat,   // (N)
    const float* __restrict__ rp,     // (16,3) [cutoff, mean, scaling]
    const float* __restrict__ ftu,    // (8)
    const int*   __restrict__ src,    // (E)
    const int*   __restrict__ dstv,   // (E)
    float*       __restrict__ out,    // (N,128)
    int n_edges, int epb)
{
    int e = blockIdx.x * blockDim.x + threadIdx.x;
    if (e >= n_edges) return;

    // one-hot type of the source node; skip edges whose type isn't in the set
    float f = __ldg(feat + __ldg(src + e));
    int t = -1;
    #pragma unroll
    for (int j = 0; j < 8; j++)
        if (f == __ldg(ftu + j)) t = j;
    if (t < 0) return;

    // radial kernel index is constant across the 16 lanes of this edge
    int q = e / epb;
    int r = e - q * epb;
    float cut  = __ldg(rp + 3 * q + 0);
    float mean = __ldg(rp + 3 * q + 1);
    float sc   = __ldg(rp + 3 * q + 2);
    float hpoc = 1.57079632679489662f / cut;   // pi/(2*cut)

    const float4* dp = reinterpret_cast<const float4*>(dist) + (r << 2); // 16 contiguous dists
    int d = __ldg(dstv + e);
    float4* op = reinterpret_cast<float4*>(out) + ((d << 5) + (t << 2)); // out + d*128 + t*16

    #pragma unroll
    for (int i = 0; i < 4; i++) {
        float4 d4 = __ldg(dp + i);
        float4 w;
        w.x = edge_weight(d4.x, cut, mean, sc, hpoc);
        w.y = edge_weight(d4.y, cut, mean, sc, hpoc);
        w.z = edge_weight(d4.z, cut, mean, sc, hpoc);
        w.w = edge_weight(d4.w, cut, mean, sc, hpoc);
        atomicAdd(op + i, w);   // sm_90+ vector red: one RED.128 per 16B
    }
}

extern "C" void kernel_launch(void* const* d_in, const int* in_sizes, int n_in,
                              void* d_out, int out_size) {
    const float* feat = (const float*)d_in[0];   // (N,1)
    const float* dist = (const float*)d_in[1];   // (E,1)
    const float* rp   = (const float*)d_in[2];   // (16,3)
    const float* ftu  = (const float*)d_in[3];   // (8,)
    const int*   src  = (const int*)d_in[4];     // (E,)
    const int*   dst  = (const int*)d_in[5];     // (E,)
    float* out = (float*)d_out;

    int n_edges = in_sizes[1];
    int epb = n_edges / 16;          // edges per radial-kernel block in flat order
    int n4 = out_size / 4;

    zero_out_kernel<<<(n4 + 255) / 256, 256>>>((float4*)out, n4);
    acnn_edge_kernel<<<(n_edges + 255) / 256, 256>>>(
        dist, feat, rp, ftu, src, dst, out, n_edges, epb);
}